// round 1
// baseline (speedup 1.0000x reference)
#include <cuda_runtime.h>

#define NN 40000        // nodes
#define NE 640000       // edges
#define D 128
#define D2 256
#define LTOK 10
#define NLAYERS 5
#define NET 10          // edge types
#define GG 512          // graphs
#define BN_EPS 1e-5f

// ---------------- scratch (static device globals; no allocation) ----------------
__device__ float g_h[NN * D];          // node features (post-BN each layer)
__device__ float g_z[NN * D];          // h + aggr accumulator
__device__ float g_mid[NN * D2];       // GIN MLP hidden
__device__ float g_z2[NN * D];         // GIN MLP output (pre-BN)
__device__ float g_sum[D];
__device__ float g_sumsq[D];
__device__ float g_mu[D];
__device__ float g_rsig[D];
__device__ float g_gsum[GG * D];
__device__ float g_gcnt[GG];

// ---------------- WordBag: h[n] = mean_l word_emb[tok[n,l]] ----------------
__global__ void wordbag_kernel(const int* __restrict__ x_tokens,
                               const int* __restrict__ ins_len,
                               const float* __restrict__ wemb) {
    int n = blockIdx.x;
    int d = threadIdx.x;
    __shared__ int toks[LTOK];
    __shared__ int len_s;
    if (d < LTOK) toks[d] = x_tokens[n * LTOK + d];
    if (d == 0) len_s = ins_len[n];
    __syncthreads();
    int len = len_s;
    float acc = 0.f;
    for (int l = 0; l < len; l++)
        acc += wemb[(long)toks[l] * D + d];
    float v = acc / (float)len;
    g_h[n * D + d] = v;
    g_z[n * D + d] = v;    // init z = h for layer 0
}

// ---------------- zero helpers ----------------
__global__ void zero_stats_kernel() {
    int d = threadIdx.x;
    g_sum[d] = 0.f;
    g_sumsq[d] = 0.f;
}

__global__ void zero_pool_kernel() {
    int i = blockIdx.x * blockDim.x + threadIdx.x;
    if (i < GG * D) g_gsum[i] = 0.f;
    if (i < GG) g_gcnt[i] = 0.f;
}

__global__ void count_kernel(const int* __restrict__ batch_ids) {
    int i = blockIdx.x * blockDim.x + threadIdx.x;
    if (i < NN) atomicAdd(&g_gcnt[batch_ids[i]], 1.0f);
}

// ---------------- edge scatter: z[dst] += h[src] + edge_emb[edge_attr] ----------------
// one warp per edge; 32 lanes x float4 = 128 channels; vector RED to global
__global__ void scatter_kernel(const int* __restrict__ edge_index,
                               const int* __restrict__ edge_attr,
                               const float* __restrict__ eemb) {
    int warp = (blockIdx.x * blockDim.x + threadIdx.x) >> 5;
    int lane = threadIdx.x & 31;
    if (warp >= NE) return;
    int src = edge_index[warp];
    int dst = edge_index[NE + warp];
    int et  = edge_attr[warp];
    const float4* h4 = (const float4*)(g_h + (long)src * D);
    const float4* e4 = (const float4*)(eemb + et * D);
    float4 hv = h4[lane];
    float4 ev = e4[lane];
    float4 m;
    m.x = hv.x + ev.x; m.y = hv.y + ev.y; m.z = hv.z + ev.z; m.w = hv.w + ev.w;
    float* zp = g_z + (long)dst * D + lane * 4;
    asm volatile("red.global.add.v4.f32 [%0], {%1,%2,%3,%4};"
                 :: "l"(zp), "f"(m.x), "f"(m.y), "f"(m.z), "f"(m.w) : "memory");
}

// ---------------- SGEMM: C[M,NC] = act(A[M,K] @ W[K,NC] + bias) ----------------
// BM=64, BN=64, BK=16; 256 threads; 4x4 register tile per thread. M=40000 (625*64 exact)
#define AS_STRIDE 68
__global__ void gemm_kernel(const float* __restrict__ A, const float* __restrict__ W,
                            const float* __restrict__ bias, float* __restrict__ C,
                            int K, int NC, int do_relu) {
    __shared__ float As[16 * AS_STRIDE];   // transposed A tile: As[k][row]
    __shared__ float Ws[16 * 64];          // Ws[k][col]
    int tid = threadIdx.x;
    int tx = tid & 15, ty = tid >> 4;
    int m0 = blockIdx.x * 64;
    int n0 = blockIdx.y * 64;
    float acc[4][4] = {};

    for (int kt = 0; kt < K; kt += 16) {
        // A tile: 64 rows x 16 cols, one float4 per thread, store transposed
        int row = tid >> 2;
        int c4  = tid & 3;
        float4 av = *(const float4*)(A + (long)(m0 + row) * K + kt + c4 * 4);
        As[(c4 * 4 + 0) * AS_STRIDE + row] = av.x;
        As[(c4 * 4 + 1) * AS_STRIDE + row] = av.y;
        As[(c4 * 4 + 2) * AS_STRIDE + row] = av.z;
        As[(c4 * 4 + 3) * AS_STRIDE + row] = av.w;
        // W tile: 16 rows x 64 cols, one float4 per thread
        int wr = tid >> 4;
        int wc = tid & 15;
        *(float4*)&Ws[wr * 64 + wc * 4] =
            *(const float4*)(W + (long)(kt + wr) * NC + n0 + wc * 4);
        __syncthreads();
#pragma unroll
        for (int k = 0; k < 16; k++) {
            float4 af = *(const float4*)&As[k * AS_STRIDE + ty * 4];
            float4 wf = *(const float4*)&Ws[k * 64 + tx * 4];
            float a[4] = {af.x, af.y, af.z, af.w};
            float w[4] = {wf.x, wf.y, wf.z, wf.w};
#pragma unroll
            for (int i = 0; i < 4; i++)
#pragma unroll
                for (int j = 0; j < 4; j++)
                    acc[i][j] += a[i] * w[j];
        }
        __syncthreads();
    }

#pragma unroll
    for (int i = 0; i < 4; i++) {
        int r = m0 + ty * 4 + i;
        float4 o;
        float* outp = C + (long)r * NC + n0 + tx * 4;
#pragma unroll
        for (int j = 0; j < 4; j++) {
            float v = acc[i][j] + bias[n0 + tx * 4 + j];
            if (do_relu) v = fmaxf(v, 0.f);
            ((float*)&o)[j] = v;
        }
        *(float4*)outp = o;
    }
}

// ---------------- BN stats over g_z2 (column sums / sumsq) ----------------
__global__ void bn_stats_kernel() {
    int d = threadIdx.x;               // 128 threads, one channel each
    int r0 = blockIdx.x * 256;
    int r1 = r0 + 256; if (r1 > NN) r1 = NN;
    float s = 0.f, sq = 0.f;
    for (int r = r0; r < r1; r++) {
        float v = g_z2[(long)r * D + d];
        s += v; sq += v * v;
    }
    atomicAdd(&g_sum[d], s);
    atomicAdd(&g_sumsq[d], sq);
}

__global__ void bn_finalize_kernel() {
    int d = threadIdx.x;
    float mu = g_sum[d] * (1.0f / NN);
    float var = g_sumsq[d] * (1.0f / NN) - mu * mu;
    g_mu[d] = mu;
    g_rsig[d] = rsqrtf(var + BN_EPS);
}

// ---------------- BN apply (+relu) ; last layer: write node_rep + pool RED ----------------
__global__ void bn_apply_kernel(const float* __restrict__ gamma,
                                const float* __restrict__ beta,
                                const int* __restrict__ batch_ids,
                                float* __restrict__ out_node,
                                int is_last) {
    int idx = blockIdx.x * blockDim.x + threadIdx.x;   // over NN*32 float4s
    if (idx >= NN * 32) return;
    int row = idx >> 5;
    int c4  = idx & 31;
    int d0  = c4 * 4;
    float4 x = *(const float4*)(g_z2 + (long)row * D + d0);
    float4 o;
    float* xv = (float*)&x;
    float* ov = (float*)&o;
#pragma unroll
    for (int j = 0; j < 4; j++) {
        int d = d0 + j;
        float v = gamma[d] * (xv[j] - g_mu[d]) * g_rsig[d] + beta[d];
        if (!is_last) v = fmaxf(v, 0.f);   // relu on all but last layer
        ov[j] = v;
    }
    if (!is_last) {
        *(float4*)(g_h + (long)row * D + d0) = o;
        *(float4*)(g_z + (long)row * D + d0) = o;   // init z=h for next layer
    } else {
        *(float4*)(out_node + (long)row * D + d0) = o;   // node_rep output
        int b = batch_ids[row];
        float* gp = g_gsum + (long)b * D + d0;
        asm volatile("red.global.add.v4.f32 [%0], {%1,%2,%3,%4};"
                     :: "l"(gp), "f"(o.x), "f"(o.y), "f"(o.z), "f"(o.w) : "memory");
    }
}

__global__ void pool_finalize_kernel(float* __restrict__ out) {
    int i = blockIdx.x * blockDim.x + threadIdx.x;   // over GG*D
    if (i >= GG * D) return;
    int g = i >> 7;
    out[i] = g_gsum[i] / fmaxf(g_gcnt[g], 1.0f);
}

// ---------------- launch ----------------
extern "C" void kernel_launch(void* const* d_in, const int* in_sizes, int n_in,
                              void* d_out, int out_size) {
    const int* x_tokens   = (const int*)d_in[0];
    const int* ins_len    = (const int*)d_in[1];
    const int* edge_index = (const int*)d_in[2];
    const int* edge_attr  = (const int*)d_in[3];
    const int* batch_ids  = (const int*)d_in[4];
    const float* wemb  = (const float*)d_in[5];
    const float* eemb  = (const float*)d_in[6];
    const float* W1    = (const float*)d_in[7];
    const float* b1    = (const float*)d_in[8];
    const float* W2    = (const float*)d_in[9];
    const float* b2    = (const float*)d_in[10];
    const float* gamma = (const float*)d_in[11];
    const float* beta  = (const float*)d_in[12];
    float* out = (float*)d_out;
    float* out_graph = out;                 // [GG, D]
    float* out_node  = out + GG * D;        // [NN, D]

    float *pz, *pmid, *pz2;
    cudaGetSymbolAddress((void**)&pz,   g_z);
    cudaGetSymbolAddress((void**)&pmid, g_mid);
    cudaGetSymbolAddress((void**)&pz2,  g_z2);

    // WordBag -> h, z
    wordbag_kernel<<<NN, 128>>>(x_tokens, ins_len, wemb);
    // pool prep (counts depend only on batch_ids)
    zero_pool_kernel<<<(GG * D + 255) / 256, 256>>>();
    count_kernel<<<(NN + 255) / 256, 256>>>(batch_ids);

    for (int l = 0; l < NLAYERS; l++) {
        int is_last = (l == NLAYERS - 1);
        zero_stats_kernel<<<1, D>>>();
        // z += scatter(h[src] + e)
        scatter_kernel<<<(NE + 7) / 8, 256>>>(edge_index, edge_attr, eemb);
        // mid = relu(z @ W1[l] + b1[l])   [NN, 256]
        gemm_kernel<<<dim3(NN / 64, D2 / 64), 256>>>(
            pz, W1 + (long)l * D * D2, b1 + (long)l * D2, pmid, D, D2, 1);
        // z2 = mid @ W2[l] + b2[l]        [NN, 128]
        gemm_kernel<<<dim3(NN / 64, D / 64), 256>>>(
            pmid, W2 + (long)l * D2 * D, b2 + (long)l * D, pz2, D2, D, 0);
        // BN train-stats + apply (+relu unless last); last layer also pools
        bn_stats_kernel<<<(NN + 255) / 256, D>>>();
        bn_finalize_kernel<<<1, D>>>();
        bn_apply_kernel<<<(NN * 32 + 255) / 256, 256>>>(
            gamma + (long)l * D, beta + (long)l * D, batch_ids, out_node, is_last);
    }

    pool_finalize_kernel<<<(GG * D + 255) / 256, 256>>>(out_graph);
}